// round 13
// baseline (speedup 1.0000x reference)
#include <cuda_runtime.h>
#include <cuda_fp16.h>
#include <cstdint>

#define NPIX  12544
#define CIN   64
#define COUT  128
#define KTOT  576
#define IMG_W 112
#define BB    16
#define NTILE 128
#define KCH   32            // one chunk = 32 channels of ONE kernel tap
#define NCH   18            // 576/32
#define ROWB  64            // bytes per smem row (32 halves)

// ---- device globals ----
__device__ __half g_spw2[NCH * COUT * KCH];   // weights, chunk-major, tap-major K, swizzle baked

__global__ void spw2_kernel(const float* __restrict__ w, const float* __restrict__ m) {
    int i = blockIdx.x * blockDim.x + threadIdx.x;
    if (i < NCH * COUT * KCH) {
        int t   = i / (COUT * KCH);
        int rem = i - t * (COUT * KCH);
        int r   = rem / KCH;
        int s   = rem - r * KCH;
        int blk = s >> 3;
        int within = s & 7;
        int oblk = blk ^ ((r >> 1) & 3);          // undo read-side swizzle
        int kic  = oblk * 8 + within;
        int rm   = t >> 1;                        // tap 0..8
        int ci   = (t & 1) * 32 + kic;            // channel 0..63
        int k    = ci * 9 + rm;
        g_spw2[i] = __float2half_rn(w[r * KTOT + k] * m[r * KTOT + k]);
    }
}

// ---- asm helpers ----
__device__ __forceinline__ uint32_t smem_u32(const void* p) {
    uint32_t a;
    asm("{ .reg .u64 t; cvta.to.shared.u64 t, %1; cvt.u32.u64 %0, t; }" : "=r"(a) : "l"(p));
    return a;
}
__device__ __forceinline__ void cpasync16(uint32_t dst, const void* src) {
    asm volatile("cp.async.cg.shared.global [%0], [%1], 16;" :: "r"(dst), "l"(src));
}
__device__ __forceinline__ void ldsm_x4(uint32_t& r0, uint32_t& r1, uint32_t& r2,
                                        uint32_t& r3, uint32_t addr) {
    asm volatile("ldmatrix.sync.aligned.m8n8.x4.shared.b16 {%0,%1,%2,%3}, [%4];"
                 : "=r"(r0), "=r"(r1), "=r"(r2), "=r"(r3) : "r"(addr));
}
__device__ __forceinline__ void mma16816(float* c, uint32_t a0, uint32_t a1,
                                         uint32_t a2, uint32_t a3,
                                         uint32_t b0, uint32_t b1) {
    asm volatile(
        "mma.sync.aligned.m16n8k16.row.col.f32.f16.f16.f32 "
        "{%0,%1,%2,%3},{%4,%5,%6,%7},{%8,%9},{%0,%1,%2,%3};"
        : "+f"(c[0]), "+f"(c[1]), "+f"(c[2]), "+f"(c[3])
        : "r"(a0), "r"(a1), "r"(a2), "r"(a3), "r"(b0), "r"(b1));
}

// ---- main kernel ----
__global__ __launch_bounds__(256, 2)
void conv_mma(const float* __restrict__ x, const float* __restrict__ bias,
              float* __restrict__ out) {
    __shared__ __align__(16) __half As[3][COUT * KCH];    // 3 x 8192B
    __shared__ __align__(16) __half Bs[3][NTILE * KCH];   // 3 x 8192B  (total 48KB)

    const int tid  = threadIdx.x;
    const int lane = tid & 31;
    const int wid  = tid >> 5;           // 0..7
    const int wm   = wid & 3;            // 32-cout tile
    const int wn   = wid >> 2;           // 64-pixel tile

    const uint32_t sA[3] = { smem_u32(&As[0][0]), smem_u32(&As[1][0]), smem_u32(&As[2][0]) };
    const uint32_t sB[3] = { smem_u32(&Bs[0][0]), smem_u32(&Bs[1][0]), smem_u32(&Bs[2][0]) };

    // ldmatrix per-lane geometry
    const int a_row = wm * 32 + ((lane >> 3) & 1) * 8 + (lane & 7);
    const int a_cb  = lane >> 4;
    const int a_swz = (a_row >> 1) & 3;
    const int b_row = wn * 64 + (lane >> 4) * 8 + (lane & 7);
    const int b_cb  = (lane >> 3) & 1;
    const int b_swz = (b_row >> 1) & 3;

    // geometry
    const int bi = blockIdx.x;
    const int b  = bi / 98;
    const int m0 = (bi - b * 98) * NTILE;
    const float* xb = x + (size_t)b * CIN * NPIX;

    // fill roles
    const int p  = tid & 127;
    const int kh = tid >> 7;
    const int gpix = m0 + p;
    const int ph = gpix / IMG_W;
    const int pw = gpix - ph * IMG_W;
    unsigned vm = 0;
    #pragma unroll
    for (int rr = 0; rr < 3; ++rr)
        #pragma unroll
        for (int jj = 0; jj < 3; ++jj)
            if ((unsigned)(ph + rr - 1) < (unsigned)IMG_W &&
                (unsigned)(pw + jj - 1) < (unsigned)IMG_W)
                vm |= 1u << (rr * 3 + jj);
    const int bswz = (p >> 1) & 3;
    const float* xpix = xb + gpix;

    float c[2][8][4];
    #pragma unroll
    for (int mt = 0; mt < 2; ++mt)
        #pragma unroll
        for (int nt = 0; nt < 8; ++nt)
            #pragma unroll
            for (int i = 0; i < 4; ++i) c[mt][nt][i] = 0.f;

    // B-fill loader: raw floats only (no cvt — deferred one iteration)
    auto b_load = [&](int t, float* v) {
        const int rm = t >> 1;
        const int dr = rm / 3;
        const int dc = rm - dr * 3;
        const bool valid = (vm >> rm) & 1u;
        const float* bp = xpix + (dr - 1) * IMG_W + (dc - 1)
                        + ((t & 1) * 32 + kh * 16) * NPIX;
        if (valid) {
            #pragma unroll
            for (int j = 0; j < 16; ++j) v[j] = __ldg(bp + (size_t)j * NPIX);
        } else {
            #pragma unroll
            for (int j = 0; j < 16; ++j) v[j] = 0.f;
        }
    };
    auto b_cvt_store = [&](int buf, const float* v) {
        uint32_t bpack[8];
        #pragma unroll
        for (int j = 0; j < 8; ++j) {
            __half2 hh = __floats2half2_rn(v[2 * j], v[2 * j + 1]);
            bpack[j] = *(uint32_t*)&hh;
        }
        char* rowp = (char*)&Bs[buf][0] + p * ROWB;
        *(uint4*)(rowp + (((kh * 2 + 0) ^ bswz) * 16)) =
            make_uint4(bpack[0], bpack[1], bpack[2], bpack[3]);
        *(uint4*)(rowp + (((kh * 2 + 1) ^ bswz) * 16)) =
            make_uint4(bpack[4], bpack[5], bpack[6], bpack[7]);
    };
    auto a_fill = [&](int t, int buf) {
        const __half* asrc = g_spw2 + (size_t)t * (COUT * KCH) + tid * 16;
        uint32_t adst = sA[buf] + tid * 32;
        cpasync16(adst, asrc);
        cpasync16(adst + 16, asrc + 8);
        asm volatile("cp.async.commit_group;" ::: "memory");
    };

    float v[16];

    // ---- prologue ----
    a_fill(0, 0);                       // group for A(0)
    b_load(0, v);
    b_cvt_store(0, v);                  // stalls on chunk-0 LDGs once (ok)
    a_fill(1, 1);                       // group for A(1)
    b_load(1, v);                       // chunk-1 LDGs in flight across chunk-0 MMA
    asm volatile("cp.async.wait_group 1;" ::: "memory");   // A(0) done
    __syncthreads();

    // ---- mainloop ----
    for (int t = 0; t < NCH; ++t) {
        const int cur = t % 3;
        const bool hasN  = (t + 1) < NCH;
        const bool hasNN = (t + 2) < NCH;

        if (hasN) {
            b_cvt_store((t + 1) % 3, v);    // data loaded last iter: no mem wait
            if (hasNN) {
                a_fill(t + 2, (t + 2) % 3); // cp.async group
                b_load(t + 2, v);           // LDGs fly through MMA(t)
            }
        }

        // mma: 2 k-steps of 16
        #pragma unroll
        for (int ks = 0; ks < 2; ++ks) {
            uint32_t a[2][4];
            #pragma unroll
            for (int mt = 0; mt < 2; ++mt)
                ldsm_x4(a[mt][0], a[mt][1], a[mt][2], a[mt][3],
                        sA[cur] + (a_row + mt * 16) * ROWB + (((ks * 2 + a_cb) ^ a_swz) * 16));
            #pragma unroll
            for (int ntp = 0; ntp < 4; ++ntp) {
                uint32_t b0, b1, b2, b3;
                ldsm_x4(b0, b1, b2, b3,
                        sB[cur] + (b_row + ntp * 16) * ROWB + (((ks * 2 + b_cb) ^ b_swz) * 16));
                #pragma unroll
                for (int mt = 0; mt < 2; ++mt) {
                    mma16816(c[mt][2 * ntp],     a[mt][0], a[mt][1], a[mt][2], a[mt][3], b0, b1);
                    mma16816(c[mt][2 * ntp + 1], a[mt][0], a[mt][1], a[mt][2], a[mt][3], b2, b3);
                }
            }
        }

        // A(t+1) must be resident before next iter's MMA
        if (hasNN) {
            asm volatile("cp.async.wait_group 1;" ::: "memory");
        } else {
            asm volatile("cp.async.wait_group 0;" ::: "memory");
        }
        __syncthreads();
    }

    // ---- epilogue ----
    const int g   = lane >> 2;
    const int tig = lane & 3;
    #pragma unroll
    for (int mt = 0; mt < 2; ++mt) {
        const int r0 = wm * 32 + mt * 16 + g;
        const float bv0 = __ldg(bias + r0);
        const float bv1 = __ldg(bias + r0 + 8);
        float* o0 = out + ((size_t)(b * COUT + r0)) * NPIX + m0;
        float* o1 = out + ((size_t)(b * COUT + r0 + 8)) * NPIX + m0;
        #pragma unroll
        for (int nt = 0; nt < 8; ++nt) {
            const int col = wn * 64 + nt * 8 + tig * 2;
            float2 v0 = { c[mt][nt][0] + bv0, c[mt][nt][1] + bv0 };
            float2 v1 = { c[mt][nt][2] + bv1, c[mt][nt][3] + bv1 };
            *(float2*)(o0 + col) = v0;
            *(float2*)(o1 + col) = v1;
        }
    }
}

extern "C" void kernel_launch(void* const* d_in, const int* in_sizes, int n_in,
                              void* d_out, int out_size) {
    const float* x      = (const float*)d_in[0];
    const float* weight = (const float*)d_in[1];
    const float* mask   = (const float*)d_in[2];
    const float* bias   = (const float*)d_in[3];
    float* out = (float*)d_out;

    spw2_kernel<<<(NCH * COUT * KCH + 255) / 256, 256>>>(weight, mask);
    conv_mma<<<BB * (NPIX / NTILE), 256>>>(x, bias, out);
}